// round 8
// baseline (speedup 1.0000x reference)
#include <cuda_runtime.h>

#define NFEAT 17
#define NEV 16
#define PPE 65536
#define NPTS (NEV * PPE)
#define T_B 0.2f
#define R2C 0.49f

#define BPE 8                 // blocks per event
#define SLICE (PPE / BPE)     // 8192 points per block
#define SCAP 7424             // smem candidate cap (mean ~6554, +24 sigma margin)
#define MAXI 64               // max greedy iterations (refs <= ~14 geometrically)

// ---- device scratch (no allocation allowed) ----
__device__ float4             g_pts[NPTS];          // (x,y,z,beta)
__device__ unsigned long long g_key[NEV * MAXI];    // per-iteration winner key
__device__ int                g_cnt[NEV * MAXI];    // per-iteration arrival counter
__device__ int                g_cidx[NEV * MAXI];   // accepted ref rows (global)
__device__ int                g_ccnt[NEV];          // ref counts

// ---------------------------------------------------------------------------
// K1: pack pts (beta=x[:,9], ccoords=x[:,14:16]) + zero barrier slots.
//     Runs FIRST so g_pts is the freshest content in L2 for condense.
// ---------------------------------------------------------------------------
__global__ void pack_kernel(const float* __restrict__ x) {
    const int gid = blockIdx.x * blockDim.x + threadIdx.x;
    if (gid < NEV * MAXI) {
        g_key[gid] = 0ULL;
        g_cnt[gid] = 0;
    }
    if (gid < NPTS) {
        const float* r = x + (long long)gid * NFEAT;
        float4 p;
        p.x = r[14]; p.y = r[15]; p.z = r[16]; p.w = r[9];
        g_pts[gid] = p;
    }
}

// ---------------------------------------------------------------------------
// K2: multi-block greedy condensation. 8 blocks/event, 1024 threads, 1 wave.
//   Candidates live in smem; live-set tracked in ping-pong u16 index lists so
//   each pass costs O(survivors). Winner exchange via L2 atomicMax on a
//   64-bit key (beta_bits<<32 | ~row) == (max beta, min idx) = jnp.argmax.
// ---------------------------------------------------------------------------
__global__ void __launch_bounds__(1024, 1) condense_kernel() {
    extern __shared__ char dyn[];
    float4*         sc  = (float4*)dyn;                       // SCAP coords+beta
    int*            si  = (int*)(sc + SCAP);                  // SCAP global rows
    unsigned short* lv0 = (unsigned short*)(si + SCAP);       // live list A
    unsigned short* lv1 = lv0 + SCAP;                         // live list B

    __shared__ unsigned long long swk[32];
    __shared__ unsigned long long s_key;
    __shared__ int s_n, s_n2;

    const int blk  = blockIdx.x;
    const int e    = blk / BPE;
    const int sub  = blk - e * BPE;
    const int t    = threadIdx.x;
    const int lane = t & 31;
    const int warp = t >> 5;
    const int base = e * PPE + sub * SLICE;

    if (t == 0) { s_n = 0; s_n2 = 0; }
    __syncthreads();

    // ---- load slice: compact candidates into smem + initial argmax key ----
    unsigned long long bk = 0ULL;
    #pragma unroll
    for (int k = 0; k < SLICE / 1024; ++k) {
        const int i = base + t + (k << 10);
        const float4 p = g_pts[i];
        const bool c = (p.w >= T_B);
        const unsigned m = __ballot_sync(0xFFFFFFFFu, c);
        int pos = 0;
        if (lane == 0 && m) pos = atomicAdd(&s_n, __popc(m));
        pos = __shfl_sync(0xFFFFFFFFu, pos, 0);
        if (c) {
            const int off = pos + __popc(m & ((1u << lane) - 1u));
            if (off < SCAP) {
                sc[off]  = p;
                si[off]  = i;
                lv0[off] = (unsigned short)off;
            }
            const unsigned long long key =
                ((unsigned long long)__float_as_uint(p.w) << 32) |
                (unsigned)(0xFFFFFFFFu - (unsigned)i);
            if (key > bk) bk = key;
        }
    }
    __syncthreads();
    int ns = s_n; if (ns > SCAP) ns = SCAP;

    unsigned short* cur = lv0;
    unsigned short* nxt = lv1;
    int count = 0;

    for (int it = 0; it < MAXI; ++it) {
        // ---- block max-reduce of keys ----
        #pragma unroll
        for (int off = 16; off > 0; off >>= 1) {
            unsigned long long o = __shfl_down_sync(0xFFFFFFFFu, bk, off);
            if (o > bk) bk = o;
        }
        if (lane == 0) swk[warp] = bk;
        __syncthreads();
        if (warp == 0) {
            bk = swk[lane];
            #pragma unroll
            for (int off = 16; off > 0; off >>= 1) {
                unsigned long long o = __shfl_down_sync(0xFFFFFFFFu, bk, off);
                if (o > bk) bk = o;
            }
            // ---- cross-block exchange (thread 0 only) ----
            if (t == 0) {
                const int slot = e * MAXI + it;
                atomicMax(&g_key[slot], bk);
                __threadfence();
                atomicAdd(&g_cnt[slot], 1);
                volatile int* vc = &g_cnt[slot];
                while (*vc < BPE) { __nanosleep(64); }
                __threadfence();
                s_key = atomicMax(&g_key[slot], 0ULL);   // RMW read: L2-coherent
            }
        }
        __syncthreads();

        const unsigned long long wk = s_key;
        const float wb = __uint_as_float((unsigned)(wk >> 32));
        if (wb < T_B) break;

        const int row = (int)(0xFFFFFFFFu - (unsigned)(wk & 0xFFFFFFFFull));
        if (sub == 0 && t == 0) g_cidx[e * MAXI + count] = row;
        ++count;

        const float4 rp = g_pts[row];   // broadcast load (L2)
        const float cx = rp.x, cy = rp.y, cz = rp.z;

        // ---- pass over live list: suppress, compact survivors, new argmax ----
        bk = 0ULL;
        const int iters = (ns + 1023) >> 10;
        for (int w = 0; w < iters; ++w) {
            const int pos = t + (w << 10);
            bool alive = false;
            int j = 0;
            unsigned long long key = 0ULL;
            if (pos < ns) {
                j = cur[pos];
                const float4 p = sc[j];
                const float dx = p.x - cx;
                const float dy = p.y - cy;
                const float dz = p.z - cz;
                alive = (dx * dx + dy * dy + dz * dz > R2C);
                if (alive) {
                    key = ((unsigned long long)__float_as_uint(p.w) << 32) |
                          (unsigned)(0xFFFFFFFFu - (unsigned)si[j]);
                }
            }
            const unsigned m = __ballot_sync(0xFFFFFFFFu, alive);
            int bp = 0;
            if (lane == 0 && m) bp = atomicAdd(&s_n2, __popc(m));
            bp = __shfl_sync(0xFFFFFFFFu, bp, 0);
            if (alive) {
                nxt[bp + __popc(m & ((1u << lane) - 1u))] = (unsigned short)j;
                if (key > bk) bk = key;
            }
        }
        __syncthreads();        // all s_n2 adds + nxt writes done
        ns = s_n2;              // every thread reads the survivor count
        __syncthreads();        // *** race fix: all reads complete before reset ***
        if (t == 0) s_n2 = 0;
        { unsigned short* tmp = cur; cur = nxt; nxt = tmp; }
        __syncthreads();        // reset visible before next iteration's adds
    }

    if (sub == 0 && t == 0) g_ccnt[e] = count;
}

// ---------------------------------------------------------------------------
// K3: zero-fill the whole output (after condense — its stores evict L2).
// ---------------------------------------------------------------------------
__global__ void zero_kernel(float* __restrict__ out, long long n) {
    const long long gid    = (long long)blockIdx.x * blockDim.x + threadIdx.x;
    const long long stride = (long long)gridDim.x * blockDim.x;
    const long long n4 = n >> 2;
    float4 z; z.x = 0.f; z.y = 0.f; z.z = 0.f; z.w = 0.f;
    for (long long j = gid; j < n4; j += stride)
        reinterpret_cast<float4*>(out)[j] = z;
    if (gid < (n & 3)) out[(n4 << 2) + gid] = 0.f;
}

// ---------------------------------------------------------------------------
// K4: scatter condensate rows + row splits.
// ---------------------------------------------------------------------------
__global__ void scatter_splits_kernel(const float* __restrict__ x,
                                      float* __restrict__ out,
                                      long long splits_off, int do_splits) {
    const int e    = blockIdx.x;
    const int cnt  = g_ccnt[e];
    const int warp = threadIdx.x >> 5;
    const int lane = threadIdx.x & 31;
    const int nw   = blockDim.x >> 5;
    for (int c = warp; c < cnt; c += nw) {
        const long long row = (long long)g_cidx[e * MAXI + c];
        if (lane < NFEAT)
            out[row * NFEAT + lane] = x[row * NFEAT + lane];
    }
    if (e == 0 && threadIdx.x == 0 && do_splits) {
        int acc = 0;
        out[splits_off] = 0.0f;
        #pragma unroll
        for (int ev = 0; ev < NEV; ++ev) {
            acc += g_ccnt[ev];
            out[splits_off + 1 + ev] = (float)acc;
        }
    }
}

// ---------------------------------------------------------------------------
extern "C" void kernel_launch(void* const* d_in, const int* in_sizes, int n_in,
                              void* d_out, int out_size) {
    const float* x   = (const float*)d_in[0];
    float*       out = (float*)d_out;
    const long long n = (long long)out_size;

    // dyn smem: 16 + 4 + 2*2 = 24 B/entry -> 178176 B (< 227 KB, 1 block/SM)
    static const size_t dyn_smem =
        (size_t)SCAP * (sizeof(float4) + sizeof(int) + 2 * sizeof(unsigned short));
    cudaFuncSetAttribute(condense_kernel,
                         cudaFuncAttributeMaxDynamicSharedMemorySize,
                         (int)dyn_smem);

    // 1) pack (leaves g_pts hot in L2) + zero barrier slots
    pack_kernel<<<NPTS / 256, 256>>>(x);

    // 2) condensation: 128 blocks (8/event), single wave, spin-barrier safe
    condense_kernel<<<NEV * BPE, 1024, dyn_smem>>>();

    // 3) zero output (71 MB of stores — deliberately after condense)
    zero_kernel<<<2048, 256>>>(out, n);

    // 4) scatter + splits
    const long long dout_elems = (long long)NPTS * NFEAT;
    const int do_splits = (n == dout_elems + NEV + 1) ? 1 : 0;
    scatter_splits_kernel<<<NEV, 512>>>(x, out, dout_elems, do_splits);
}

// round 9
// speedup vs baseline: 1.0036x; 1.0036x over previous
#include <cuda_runtime.h>

#define NFEAT 17
#define NEV 16
#define PPE 65536
#define NPTS (NEV * PPE)
#define T_B 0.2f
#define R2C 0.49f

#define BPE 8                 // blocks per event (one 8192-pt slice each)
#define SLICE (PPE / BPE)
#define SCAP 7424             // smem candidate cap (mean ~6554, +24 sigma)
#define MAXI 64               // max greedy iterations (refs <= ~27 geometrically)
#define NSLOT (NEV * MAXI * BPE * 4)   // publish slots: 4 u64 words each

// ---- device scratch (no allocation allowed) ----
__device__ float4             g_pts[NPTS];    // (x,y,z,beta)
__device__ unsigned long long g_pub[NSLOT];   // [e][it][sub]{key,xy,z,pad}
__device__ int                g_ccnt[NEV];
__device__ int                g_done;

// ---------------------------------------------------------------------------
// K1: zero output + pack pts + zero publish slots/done counter.
// ---------------------------------------------------------------------------
__global__ void zero_pack_kernel(const float* __restrict__ x,
                                 float* __restrict__ out, long long n) {
    const long long gid    = (long long)blockIdx.x * blockDim.x + threadIdx.x;
    const long long stride = (long long)gridDim.x * blockDim.x;

    const long long n4 = n >> 2;
    float4 z; z.x = 0.f; z.y = 0.f; z.z = 0.f; z.w = 0.f;
    for (long long j = gid; j < n4; j += stride)
        reinterpret_cast<float4*>(out)[j] = z;
    if (gid < (n & 3)) out[(n4 << 2) + gid] = 0.f;

    if (gid < NSLOT) g_pub[gid] = 0ULL;
    if (gid == 0)    g_done = 0;

    if (gid < NPTS) {
        const float* r = x + gid * NFEAT;
        float4 p;
        p.x = r[14]; p.y = r[15]; p.z = r[16]; p.w = r[9];
        g_pts[gid] = p;
    }
}

// ---------------------------------------------------------------------------
// K2: condensation + scatter + splits. 8 blocks/event, 1024 thr, single wave.
//   Key = (beta_bits<<32)|(~row): max key == (max beta, min idx) == jnp.argmax.
//   Cross-block exchange: publish-poll mailbox (data, fence, key-as-flag);
//   8 lanes poll the 8 slots (256 contiguous bytes) in parallel.
// ---------------------------------------------------------------------------
__global__ void __launch_bounds__(1024, 1)
condense_kernel(const float* __restrict__ x, float* __restrict__ out,
                long long splits_off, int do_splits) {
    extern __shared__ char dyn[];
    float4*         sc  = (float4*)dyn;                  // SCAP coords+beta
    int*            si  = (int*)(sc + SCAP);             // SCAP global rows
    unsigned short* lv0 = (unsigned short*)(si + SCAP);  // live list A
    unsigned short* lv1 = lv0 + SCAP;                    // live list B

    __shared__ unsigned long long swk[32];
    __shared__ int swp[32];
    __shared__ unsigned long long s_key;
    __shared__ float s_cx, s_cy, s_cz;
    __shared__ int s_n, s_n2, s_rows[MAXI];

    const int blk  = blockIdx.x;
    const int e    = blk / BPE;
    const int sub  = blk - e * BPE;
    const int t    = threadIdx.x;
    const int lane = t & 31;
    const int warp = t >> 5;
    const int base = e * PPE + sub * SLICE;

    if (t == 0) { s_n = 0; s_n2 = 0; }
    __syncthreads();

    // ---- load slice: compact candidates into smem + initial (key,pos) ----
    unsigned long long bk = 0ULL;
    int bp = -1;
    #pragma unroll
    for (int k = 0; k < SLICE / 1024; ++k) {
        const int i = base + t + (k << 10);
        const float4 p = g_pts[i];
        const bool c = (p.w >= T_B);
        const unsigned m = __ballot_sync(0xFFFFFFFFu, c);
        int pos = 0;
        if (lane == 0 && m) pos = atomicAdd(&s_n, __popc(m));
        pos = __shfl_sync(0xFFFFFFFFu, pos, 0);
        if (c) {
            const int off = pos + __popc(m & ((1u << lane) - 1u));
            if (off < SCAP) {
                sc[off]  = p;
                si[off]  = i;
                lv0[off] = (unsigned short)off;
                const unsigned long long key =
                    ((unsigned long long)__float_as_uint(p.w) << 32) |
                    (unsigned)(0xFFFFFFFFu - (unsigned)i);
                if (key > bk) { bk = key; bp = off; }
            }
        }
    }
    __syncthreads();
    int ns = s_n; if (ns > SCAP) ns = SCAP;

    unsigned short* cur = lv0;
    unsigned short* nxt = lv1;
    int count = 0;

    for (int it = 0; it < MAXI; ++it) {
        // ---- block argmax reduce of (key,pos) ----
        #pragma unroll
        for (int off = 16; off > 0; off >>= 1) {
            unsigned long long ok = __shfl_down_sync(0xFFFFFFFFu, bk, off);
            int op = __shfl_down_sync(0xFFFFFFFFu, bp, off);
            if (ok > bk) { bk = ok; bp = op; }
        }
        if (lane == 0) { swk[warp] = bk; swp[warp] = bp; }
        __syncthreads();
        if (warp == 0) {
            bk = swk[lane]; bp = swp[lane];
            #pragma unroll
            for (int off = 16; off > 0; off >>= 1) {
                unsigned long long ok = __shfl_down_sync(0xFFFFFFFFu, bk, off);
                int op = __shfl_down_sync(0xFFFFFFFFu, bp, off);
                if (ok > bk) { bk = ok; bp = op; }
            }
            const int slotbase = (e * MAXI + it) * BPE * 4;
            // ---- publish own winner: data words, fence, key flag ----
            if (lane == 0) {
                volatile unsigned long long* own = g_pub + slotbase + sub * 4;
                float4 w;
                if (bp >= 0) w = sc[bp];
                else { w.x = 0.f; w.y = 0.f; w.z = 0.f; w.w = 0.f; }
                own[1] = ((unsigned long long)__float_as_uint(w.x) << 32) |
                         __float_as_uint(w.y);
                own[2] = (unsigned long long)__float_as_uint(w.z);
                __threadfence();
                own[0] = bk ? bk : 1ULL;        // sentinel for empty block
            }
            __syncwarp();
            // ---- poll all 8 slots in parallel (lanes 0..7) ----
            unsigned long long pk = 0ULL, pxy = 0ULL, pzz = 0ULL;
            if (lane < 8) {
                volatile unsigned long long* sl = g_pub + slotbase + lane * 4;
                while ((pk = sl[0]) == 0ULL) { }
                pxy = sl[1];
                pzz = sl[2];
            }
            #pragma unroll
            for (int off = 4; off > 0; off >>= 1) {
                unsigned long long ok  = __shfl_down_sync(0xFFFFFFFFu, pk, off);
                unsigned long long oxy = __shfl_down_sync(0xFFFFFFFFu, pxy, off);
                unsigned long long ozz = __shfl_down_sync(0xFFFFFFFFu, pzz, off);
                if (ok > pk) { pk = ok; pxy = oxy; pzz = ozz; }
            }
            if (lane == 0) {
                s_key = pk;
                s_cx = __uint_as_float((unsigned)(pxy >> 32));
                s_cy = __uint_as_float((unsigned)pxy);
                s_cz = __uint_as_float((unsigned)pzz);
            }
        }
        __syncthreads();

        const unsigned long long wk = s_key;
        const float wb = __uint_as_float((unsigned)(wk >> 32));
        if (wb < T_B) break;

        const int row = (int)(0xFFFFFFFFu - (unsigned)(wk & 0xFFFFFFFFull));
        if (sub == 0 && t == 0) s_rows[count] = row;
        ++count;

        const float cx = s_cx, cy = s_cy, cz = s_cz;

        // ---- live-list pass: suppress, compact survivors, new (key,pos) ----
        bk = 0ULL; bp = -1;
        const int iters = (ns + 1023) >> 10;
        for (int w = 0; w < iters; ++w) {
            const int pos = t + (w << 10);
            bool alive = false;
            int j = 0;
            unsigned long long key = 0ULL;
            if (pos < ns) {
                j = cur[pos];
                const float4 p = sc[j];
                const float dx = p.x - cx;
                const float dy = p.y - cy;
                const float dz = p.z - cz;
                alive = (dx * dx + dy * dy + dz * dz > R2C);
                if (alive)
                    key = ((unsigned long long)__float_as_uint(p.w) << 32) |
                          (unsigned)(0xFFFFFFFFu - (unsigned)si[j]);
            }
            const unsigned m = __ballot_sync(0xFFFFFFFFu, alive);
            int wp2 = 0;
            if (lane == 0 && m) wp2 = atomicAdd(&s_n2, __popc(m));
            wp2 = __shfl_sync(0xFFFFFFFFu, wp2, 0);
            if (alive) {
                nxt[wp2 + __popc(m & ((1u << lane) - 1u))] = (unsigned short)j;
                if (key > bk) { bk = key; bp = j; }
            }
        }
        __syncthreads();          // all adds + nxt writes done
        ns = s_n2;                // everyone reads the count
        __syncthreads();          // reads complete before reset
        if (t == 0) s_n2 = 0;
        { unsigned short* tmp = cur; cur = nxt; nxt = tmp; }
        __syncthreads();          // reset visible before next adds
    }

    // ---- tail: scatter this event's rows (sub 0) + splits (last event) ----
    __syncthreads();
    if (sub == 0) {
        for (int c = warp; c < count; c += 32) {
            const long long row = (long long)s_rows[c];
            if (lane < NFEAT)
                out[row * NFEAT + lane] = x[row * NFEAT + lane];
        }
        if (t == 0) {
            *(volatile int*)&g_ccnt[e] = count;
            __threadfence();
            if (do_splits) {
                const int old = atomicAdd(&g_done, 1);
                if (old == NEV - 1) {
                    __threadfence();
                    int acc = 0;
                    out[splits_off] = 0.0f;
                    #pragma unroll
                    for (int ev = 0; ev < NEV; ++ev) {
                        acc += *(volatile int*)&g_ccnt[ev];
                        out[splits_off + 1 + ev] = (float)acc;
                    }
                }
            }
        }
    }
}

// ---------------------------------------------------------------------------
extern "C" void kernel_launch(void* const* d_in, const int* in_sizes, int n_in,
                              void* d_out, int out_size) {
    const float* x   = (const float*)d_in[0];
    float*       out = (float*)d_out;
    const long long n = (long long)out_size;

    // dyn smem: 16 + 4 + 2*2 = 24 B/entry -> 178176 B (1 block/SM, 1 wave)
    static const size_t dyn_smem =
        (size_t)SCAP * (sizeof(float4) + sizeof(int) + 2 * sizeof(unsigned short));
    cudaFuncSetAttribute(condense_kernel,
                         cudaFuncAttributeMaxDynamicSharedMemorySize,
                         (int)dyn_smem);

    // 1) fused zero + pack + slot init
    zero_pack_kernel<<<NPTS / 256, 256>>>(x, out, n);

    // 2) condense + scatter + splits (128 blocks: single wave, poll-safe)
    const long long dout_elems = (long long)NPTS * NFEAT;
    const int do_splits = (n == dout_elems + NEV + 1) ? 1 : 0;
    condense_kernel<<<NEV * BPE, 1024, dyn_smem>>>(x, out, dout_elems, do_splits);
}

// round 10
// speedup vs baseline: 1.1972x; 1.1929x over previous
#include <cuda_runtime.h>

#define NFEAT 17
#define NEV 16
#define PPE 65536
#define NPTS (NEV * PPE)
#define T_B 0.2f
#define R2C 0.49f

#define BPE 8                 // blocks per event (one 8192-pt slice each)
#define SLICE (PPE / BPE)
#define PPT 8                 // points per thread (SLICE / 1024), register-resident
#define MAXI 64               // max greedy iterations (refs <= ~30 geometrically)
#define NKEY (NEV * MAXI * BPE)

// ---- device scratch (no allocation allowed) ----
__device__ float4             g_pts[NPTS];   // (x,y,z,beta)
__device__ unsigned long long g_key[NKEY];   // mailbox: one u64 key per block/iter
__device__ int                g_ccnt[NEV];
__device__ int                g_done;

// ---------------------------------------------------------------------------
// K1: zero output + pack pts + zero mailbox/done counter.
// ---------------------------------------------------------------------------
__global__ void zero_pack_kernel(const float* __restrict__ x,
                                 float* __restrict__ out, long long n) {
    const long long gid    = (long long)blockIdx.x * blockDim.x + threadIdx.x;
    const long long stride = (long long)gridDim.x * blockDim.x;

    const long long n4 = n >> 2;
    float4 z; z.x = 0.f; z.y = 0.f; z.z = 0.f; z.w = 0.f;
    for (long long j = gid; j < n4; j += stride)
        reinterpret_cast<float4*>(out)[j] = z;
    if (gid < (n & 3)) out[(n4 << 2) + gid] = 0.f;

    if (gid < NKEY) g_key[gid] = 0ULL;
    if (gid == 0)   g_done = 0;

    if (gid < NPTS) {
        const float* r = x + gid * NFEAT;
        float4 p;
        p.x = r[14]; p.y = r[15]; p.z = r[16]; p.w = r[9];
        g_pts[gid] = p;
    }
}

// ---------------------------------------------------------------------------
// K2: condensation + scatter + splits. 8 blocks/event, 1024 thr, single wave.
//   Candidates are REGISTER-resident: 8 float4 per thread; suppression sets
//   w=-1. Key = (beta_bits<<32)|(~row): max key == (max beta, min idx) ==
//   jnp.argmax. Exchange: each block volatile-stores its 8B key (atomic,
//   key-as-flag, fresh slot per iteration); 8 lanes poll the 8 slots; winner
//   coords fetched once from g_pts[row] (L2 broadcast).
// ---------------------------------------------------------------------------
__global__ void __launch_bounds__(1024, 1)
condense_kernel(const float* __restrict__ x, float* __restrict__ out,
                long long splits_off, int do_splits) {
    __shared__ unsigned long long swk[32];
    __shared__ unsigned long long s_key;
    __shared__ float4 s_ref;
    __shared__ int s_rows[MAXI];

    const int blk  = blockIdx.x;
    const int e    = blk / BPE;
    const int sub  = blk - e * BPE;
    const int t    = threadIdx.x;
    const int lane = t & 31;
    const int warp = t >> 5;
    const int base = e * PPE + sub * SLICE;

    // ---- load slice into registers + initial per-thread argmax key ----
    float4 p[PPT];
    unsigned long long bk = 0ULL;
    #pragma unroll
    for (int k = 0; k < PPT; ++k) {
        const int i = base + t + (k << 10);
        p[k] = g_pts[i];
        if (p[k].w >= T_B) {
            const unsigned long long key =
                ((unsigned long long)__float_as_uint(p[k].w) << 32) |
                (unsigned)(~(unsigned)i);
            if (key > bk) bk = key;
        } else {
            p[k].w = -1.0f;   // dead
        }
    }

    int count = 0;

    for (int it = 0; it < MAXI; ++it) {
        // ---- block argmax of keys: warp shuffle + 32-entry smem ----
        #pragma unroll
        for (int off = 16; off > 0; off >>= 1) {
            const unsigned long long o = __shfl_down_sync(0xFFFFFFFFu, bk, off);
            if (o > bk) bk = o;
        }
        if (lane == 0) swk[warp] = bk;
        __syncthreads();
        if (warp == 0) {
            unsigned long long v = swk[lane];
            #pragma unroll
            for (int off = 16; off > 0; off >>= 1) {
                const unsigned long long o = __shfl_down_sync(0xFFFFFFFFu, v, off);
                if (o > v) v = o;
            }
            // ---- publish own key (8B volatile store = atomic, flag=nonzero) ----
            if (lane == 0) {
                const unsigned long long pubk = v ? v : 1ULL;  // sentinel: empty
                unsigned long long* own = g_key + (e * MAXI + it) * BPE + sub;
                asm volatile("st.volatile.global.b64 [%0], %1;"
                             :: "l"(own), "l"(pubk) : "memory");
            }
            __syncwarp();
            // ---- poll all 8 slots in parallel (lanes 0..7) ----
            unsigned long long pk = 0ULL;
            if (lane < 8) {
                const unsigned long long* sl = g_key + (e * MAXI + it) * BPE + lane;
                do {
                    asm volatile("ld.volatile.global.b64 %0, [%1];"
                                 : "=l"(pk) : "l"(sl));
                } while (pk == 0ULL);
            }
            #pragma unroll
            for (int off = 4; off > 0; off >>= 1) {
                const unsigned long long o = __shfl_down_sync(0xFFFFFFFFu, pk, off);
                if (o > pk) pk = o;
            }
            if (lane == 0) {
                s_key = pk;
                const float pb = __uint_as_float((unsigned)(pk >> 32));
                if (pb >= T_B) {
                    const int row = (int)(~(unsigned)(pk & 0xFFFFFFFFull));
                    s_ref = g_pts[row];          // L2 broadcast (same line, 8 blocks)
                }
            }
        }
        __syncthreads();

        const unsigned long long wk = s_key;
        const float wb = __uint_as_float((unsigned)(wk >> 32));
        if (wb < T_B) break;

        if (t == 0) s_rows[count] = (int)(~(unsigned)(wk & 0xFFFFFFFFull));
        ++count;

        const float cx = s_ref.x, cy = s_ref.y, cz = s_ref.z;

        // ---- register pass: suppress + next per-thread key (no smem, no sync) ----
        bk = 0ULL;
        #pragma unroll
        for (int k = 0; k < PPT; ++k) {
            const float w = p[k].w;
            if (w >= 0.0f) {
                const float dx = p[k].x - cx;
                const float dy = p[k].y - cy;
                const float dz = p[k].z - cz;
                const float d2 = dx * dx + dy * dy + dz * dz;
                if (d2 <= R2C) {
                    p[k].w = -1.0f;
                } else {
                    const int i = base + t + (k << 10);
                    const unsigned long long key =
                        ((unsigned long long)__float_as_uint(w) << 32) |
                        (unsigned)(~(unsigned)i);
                    if (key > bk) bk = key;
                }
            }
        }
    }

    // ---- tail: scatter this event's rows (sub 0) + splits (last event) ----
    __syncthreads();
    if (sub == 0) {
        for (int c = warp; c < count; c += 32) {
            const long long row = (long long)s_rows[c];
            if (lane < NFEAT)
                out[row * NFEAT + lane] = x[row * NFEAT + lane];
        }
        if (t == 0) {
            *(volatile int*)&g_ccnt[e] = count;
            __threadfence();
            if (do_splits) {
                const int old = atomicAdd(&g_done, 1);
                if (old == NEV - 1) {
                    __threadfence();
                    int acc = 0;
                    out[splits_off] = 0.0f;
                    #pragma unroll
                    for (int ev = 0; ev < NEV; ++ev) {
                        acc += *(volatile int*)&g_ccnt[ev];
                        out[splits_off + 1 + ev] = (float)acc;
                    }
                }
            }
        }
    }
}

// ---------------------------------------------------------------------------
extern "C" void kernel_launch(void* const* d_in, const int* in_sizes, int n_in,
                              void* d_out, int out_size) {
    const float* x   = (const float*)d_in[0];
    float*       out = (float*)d_out;
    const long long n = (long long)out_size;

    // 1) fused zero + pack + mailbox init
    zero_pack_kernel<<<NPTS / 256, 256>>>(x, out, n);

    // 2) condense + scatter + splits (128 blocks: single wave, poll-safe)
    const long long dout_elems = (long long)NPTS * NFEAT;
    const int do_splits = (n == dout_elems + NEV + 1) ? 1 : 0;
    condense_kernel<<<NEV * BPE, 1024>>>(x, out, dout_elems, do_splits);
}